// round 7
// baseline (speedup 1.0000x reference)
#include <cuda_runtime.h>
#include <math.h>

#define DD 64
#define HH 256
#define MT 32
#define NPS 10

// ---- shared memory layout (float offsets) ----
#define OFF_W2C   0            // W2 transposed copy: [64][260]  (W2c[d][h] = W2[h][d])
#define W2C_STRIDE 260
#define OFF_R2    16640        // multi-use: W1x nat / W1u nat / W2 nat / W1uT [256][66]
#define W1UT_STRIDE 66
#define OFF_S     33536        // s = elu'(pre): [32][256]
#define OFF_T     41728        // scratch t tile: [32][256]
#define OFF_WT    49920        // w transposed: [64][36]  (wT[d][m])
#define WT_STRIDE 36
#define OFF_BUF   52224        // xT then uT: [64][33]
#define BUF_STRIDE 33
#define OFF_EPS   54336        // eps natural: [32][64]
#define SMEM_FLOATS 56384      // 225536 bytes

__global__ __launch_bounds__(256, 1)
void ires_fused_kernel(const float* __restrict__ gx, const float* __restrict__ gu,
                       const float* __restrict__ glogpx, const float* __restrict__ geps,
                       const float* __restrict__ gW1x, const float* __restrict__ gW1u,
                       const float* __restrict__ gb1, const float* __restrict__ gW2,
                       const float* __restrict__ gb2,
                       float* __restrict__ outv, float* __restrict__ outlp)
{
    extern __shared__ float sm[];
    const int tid = threadIdx.x;
    const int tm  = tid >> 5;   // warp id 0..7 -> rows 4*tm..4*tm+3
    const int ln  = tid & 31;   // lane
    const int m0  = blockIdx.x * MT;

    // ---------------- step 0: loads ----------------
    // W1x natural -> R2
    #pragma unroll 4
    for (int i = 0; i < 64; i++) {
        int idx = tid + i * 256;
        sm[OFF_R2 + idx] = gW1x[idx];
    }
    // W2 transposed -> W2C  (W2 natural is [H][D] row-major)
    #pragma unroll 4
    for (int i = 0; i < 64; i++) {
        int idx = tid + i * 256;
        int h = idx >> 6, d = idx & 63;
        sm[OFF_W2C + d * W2C_STRIDE + h] = gW2[idx];
    }
    // x transposed -> BUF
    #pragma unroll
    for (int i = 0; i < 8; i++) {
        int idx = tid + i * 256;
        int m = idx >> 6, d = idx & 63;
        sm[OFF_BUF + d * BUF_STRIDE + m] = gx[(size_t)m0 * DD + idx];
    }
    // eps natural -> EPS, eps transposed -> WT (w_0 = eps)
    #pragma unroll
    for (int i = 0; i < 8; i++) {
        int idx = tid + i * 256;
        float e = geps[(size_t)m0 * DD + idx];
        sm[OFF_EPS + idx] = e;
        int m = idx >> 6, d = idx & 63;
        sm[OFF_WT + d * WT_STRIDE + m] = e;
    }
    __syncthreads();

    // ---------------- phase A: pre = x@W1x ----------------
    float pr[4][8];
    #pragma unroll
    for (int i = 0; i < 4; i++)
        #pragma unroll
        for (int j = 0; j < 8; j++) pr[i][j] = 0.f;

    #pragma unroll 8
    for (int d = 0; d < 64; d++) {
        float av[4];
        #pragma unroll
        for (int i = 0; i < 4; i++) av[i] = sm[OFF_BUF + d * BUF_STRIDE + 4 * tm + i];
        float4 b04 = *(const float4*)&sm[OFF_R2 + d * HH + 8 * ln];
        float4 b14 = *(const float4*)&sm[OFF_R2 + d * HH + 8 * ln + 4];
        float bv[8] = {b04.x, b04.y, b04.z, b04.w, b14.x, b14.y, b14.z, b14.w};
        #pragma unroll
        for (int i = 0; i < 4; i++)
            #pragma unroll
            for (int j = 0; j < 8; j++)
                pr[i][j] = fmaf(av[i], bv[j], pr[i][j]);
    }
    __syncthreads();

    // load W1u natural -> R2, uT -> BUF
    #pragma unroll 4
    for (int i = 0; i < 64; i++) {
        int idx = tid + i * 256;
        sm[OFF_R2 + idx] = gW1u[idx];
    }
    #pragma unroll
    for (int i = 0; i < 8; i++) {
        int idx = tid + i * 256;
        int m = idx >> 6, d = idx & 63;
        sm[OFF_BUF + d * BUF_STRIDE + m] = gu[(size_t)m0 * DD + idx];
    }
    __syncthreads();

    // pre += u@W1u
    #pragma unroll 8
    for (int d = 0; d < 64; d++) {
        float av[4];
        #pragma unroll
        for (int i = 0; i < 4; i++) av[i] = sm[OFF_BUF + d * BUF_STRIDE + 4 * tm + i];
        float4 b04 = *(const float4*)&sm[OFF_R2 + d * HH + 8 * ln];
        float4 b14 = *(const float4*)&sm[OFF_R2 + d * HH + 8 * ln + 4];
        float bv[8] = {b04.x, b04.y, b04.z, b04.w, b14.x, b14.y, b14.z, b14.w};
        #pragma unroll
        for (int i = 0; i < 4; i++)
            #pragma unroll
            for (int j = 0; j < 8; j++)
                pr[i][j] = fmaf(av[i], bv[j], pr[i][j]);
    }

    // + b1, then h = elu(pre) -> T,  s = elu'(pre) -> S
    {
        float4 bb0 = *(const float4*)&gb1[8 * ln];
        float4 bb1 = *(const float4*)&gb1[8 * ln + 4];
        float bb[8] = {bb0.x, bb0.y, bb0.z, bb0.w, bb1.x, bb1.y, bb1.z, bb1.w};
        #pragma unroll
        for (int i = 0; i < 4; i++) {
            float hv[8], sv[8];
            #pragma unroll
            for (int j = 0; j < 8; j++) {
                float p = pr[i][j] + bb[j];
                if (p > 0.f) { hv[j] = p; sv[j] = 1.f; }
                else { float em = expm1f(p); hv[j] = em; sv[j] = em + 1.f; }
            }
            int base = (4 * tm + i) * HH + 8 * ln;
            *(float4*)&sm[OFF_T + base]     = make_float4(hv[0], hv[1], hv[2], hv[3]);
            *(float4*)&sm[OFF_T + base + 4] = make_float4(hv[4], hv[5], hv[6], hv[7]);
            *(float4*)&sm[OFF_S + base]     = make_float4(sv[0], sv[1], sv[2], sv[3]);
            *(float4*)&sm[OFF_S + base + 4] = make_float4(sv[4], sv[5], sv[6], sv[7]);
        }
    }
    __syncthreads();

    // load W2 natural -> R2 (for g GEMM)
    #pragma unroll 4
    for (int i = 0; i < 64; i++) {
        int idx = tid + i * 256;
        sm[OFF_R2 + idx] = gW2[idx];
    }
    __syncthreads();

    // ---------------- g = h@W2 + b2 ; v = u + g ----------------
    {
        float ga[4][2];
        #pragma unroll
        for (int i = 0; i < 4; i++) { ga[i][0] = 0.f; ga[i][1] = 0.f; }
        #pragma unroll 2
        for (int h = 0; h < HH; h += 4) {
            float4 a0 = *(const float4*)&sm[OFF_T + (4 * tm + 0) * HH + h];
            float4 a1 = *(const float4*)&sm[OFF_T + (4 * tm + 1) * HH + h];
            float4 a2 = *(const float4*)&sm[OFF_T + (4 * tm + 2) * HH + h];
            float4 a3 = *(const float4*)&sm[OFF_T + (4 * tm + 3) * HH + h];
#define GSTEP(hh, c0, c1, c2, c3) { \
            float2 b = *(const float2*)&sm[OFF_R2 + (h + hh) * DD + 2 * ln]; \
            ga[0][0] = fmaf(c0, b.x, ga[0][0]); ga[0][1] = fmaf(c0, b.y, ga[0][1]); \
            ga[1][0] = fmaf(c1, b.x, ga[1][0]); ga[1][1] = fmaf(c1, b.y, ga[1][1]); \
            ga[2][0] = fmaf(c2, b.x, ga[2][0]); ga[2][1] = fmaf(c2, b.y, ga[2][1]); \
            ga[3][0] = fmaf(c3, b.x, ga[3][0]); ga[3][1] = fmaf(c3, b.y, ga[3][1]); }
            GSTEP(0, a0.x, a1.x, a2.x, a3.x)
            GSTEP(1, a0.y, a1.y, a2.y, a3.y)
            GSTEP(2, a0.z, a1.z, a2.z, a3.z)
            GSTEP(3, a0.w, a1.w, a2.w, a3.w)
#undef GSTEP
        }
        float2 b2v = *(const float2*)&gb2[2 * ln];
        #pragma unroll
        for (int i = 0; i < 4; i++) {
            size_t off = (size_t)(m0 + 4 * tm + i) * DD + 2 * ln;
            float2 uu = *(const float2*)&gu[off];
            float2 vv = make_float2(uu.x + ga[i][0] + b2v.x, uu.y + ga[i][1] + b2v.y);
            *(float2*)&outv[off] = vv;
        }
    }
    __syncthreads();

    // load W1u transposed -> R2  (W1uT[h][d], stride 66)
    #pragma unroll 4
    for (int i = 0; i < 64; i++) {
        int idx = tid + i * 256;
        int d = idx >> 8, h = idx & 255;
        sm[OFF_R2 + h * W1UT_STRIDE + d] = gW1u[idx];
    }
    // eps registers for the dot products
    float er[4][2];
    #pragma unroll
    for (int i = 0; i < 4; i++) {
        float2 e2 = *(const float2*)&sm[OFF_EPS + (4 * tm + i) * DD + 2 * ln];
        er[i][0] = e2.x; er[i][1] = e2.y;
    }
    float ldacc[4] = {0.f, 0.f, 0.f, 0.f};
    __syncthreads();

    // ---------------- power series: 10 VJP iterations ----------------
    for (int k = 1; k <= NPS; k++) {
        // GEMM1: t[m][h] = s[m][h] * sum_d w[m][d] * W2[h][d]
        float acc[4][8];
        #pragma unroll
        for (int i = 0; i < 4; i++)
            #pragma unroll
            for (int j = 0; j < 8; j++) acc[i][j] = 0.f;

        #pragma unroll 8
        for (int d = 0; d < 64; d++) {
            float4 a4  = *(const float4*)&sm[OFF_WT + d * WT_STRIDE + 4 * tm];
            float4 b04 = *(const float4*)&sm[OFF_W2C + d * W2C_STRIDE + 8 * ln];
            float4 b14 = *(const float4*)&sm[OFF_W2C + d * W2C_STRIDE + 8 * ln + 4];
            float av[4] = {a4.x, a4.y, a4.z, a4.w};
            float bv[8] = {b04.x, b04.y, b04.z, b04.w, b14.x, b14.y, b14.z, b14.w};
            #pragma unroll
            for (int i = 0; i < 4; i++)
                #pragma unroll
                for (int j = 0; j < 8; j++)
                    acc[i][j] = fmaf(av[i], bv[j], acc[i][j]);
        }
        #pragma unroll
        for (int i = 0; i < 4; i++) {
            int base = (4 * tm + i) * HH + 8 * ln;
            float4 s0 = *(const float4*)&sm[OFF_S + base];
            float4 s1 = *(const float4*)&sm[OFF_S + base + 4];
            *(float4*)&sm[OFF_T + base] =
                make_float4(acc[i][0] * s0.x, acc[i][1] * s0.y, acc[i][2] * s0.z, acc[i][3] * s0.w);
            *(float4*)&sm[OFF_T + base + 4] =
                make_float4(acc[i][4] * s1.x, acc[i][5] * s1.y, acc[i][6] * s1.z, acc[i][7] * s1.w);
        }
        __syncthreads();

        // GEMM2: w_new[m][a] = sum_h t[m][h] * W1u[a][h]   (W1uT[h][a])
        float w2a[4][2];
        #pragma unroll
        for (int i = 0; i < 4; i++) { w2a[i][0] = 0.f; w2a[i][1] = 0.f; }

        #pragma unroll 2
        for (int h = 0; h < HH; h += 4) {
            float4 a0 = *(const float4*)&sm[OFF_T + (4 * tm + 0) * HH + h];
            float4 a1 = *(const float4*)&sm[OFF_T + (4 * tm + 1) * HH + h];
            float4 a2 = *(const float4*)&sm[OFF_T + (4 * tm + 2) * HH + h];
            float4 a3 = *(const float4*)&sm[OFF_T + (4 * tm + 3) * HH + h];
#define G2STEP(hh, c0, c1, c2, c3) { \
            float2 b = *(const float2*)&sm[OFF_R2 + (h + hh) * W1UT_STRIDE + 2 * ln]; \
            w2a[0][0] = fmaf(c0, b.x, w2a[0][0]); w2a[0][1] = fmaf(c0, b.y, w2a[0][1]); \
            w2a[1][0] = fmaf(c1, b.x, w2a[1][0]); w2a[1][1] = fmaf(c1, b.y, w2a[1][1]); \
            w2a[2][0] = fmaf(c2, b.x, w2a[2][0]); w2a[2][1] = fmaf(c2, b.y, w2a[2][1]); \
            w2a[3][0] = fmaf(c3, b.x, w2a[3][0]); w2a[3][1] = fmaf(c3, b.y, w2a[3][1]); }
            G2STEP(0, a0.x, a1.x, a2.x, a3.x)
            G2STEP(1, a0.y, a1.y, a2.y, a3.y)
            G2STEP(2, a0.z, a1.z, a2.z, a3.z)
            G2STEP(3, a0.w, a1.w, a2.w, a3.w)
#undef G2STEP
        }

        // logdet += coeff * sum_a w_new[m][a] * eps[m][a]
        float coeff = ((k & 1) ? 1.0f : -1.0f) / (float)k;
        float part[4];
        #pragma unroll
        for (int i = 0; i < 4; i++)
            part[i] = w2a[i][0] * er[i][0] + w2a[i][1] * er[i][1];
        #pragma unroll
        for (int o = 16; o > 0; o >>= 1) {
            #pragma unroll
            for (int i = 0; i < 4; i++)
                part[i] += __shfl_xor_sync(0xffffffffu, part[i], o);
        }
        #pragma unroll
        for (int i = 0; i < 4; i++) ldacc[i] = fmaf(coeff, part[i], ldacc[i]);

        // store w_new transposed for next GEMM1
        #pragma unroll
        for (int j = 0; j < 2; j++)
            #pragma unroll
            for (int i = 0; i < 4; i++)
                sm[OFF_WT + (2 * ln + j) * WT_STRIDE + 4 * tm + i] = w2a[i][j];
        __syncthreads();
    }

    if (ln == 0) {
        #pragma unroll
        for (int i = 0; i < 4; i++) {
            int m = m0 + 4 * tm + i;
            outlp[m] = glogpx[m] - ldacc[i];
        }
    }
}

extern "C" void kernel_launch(void* const* d_in, const int* in_sizes, int n_in,
                              void* d_out, int out_size)
{
    const float* gx     = (const float*)d_in[0];
    const float* gu     = (const float*)d_in[1];
    const float* glogpx = (const float*)d_in[2];
    const float* geps   = (const float*)d_in[3];
    const float* gW1x   = (const float*)d_in[4];
    const float* gW1u   = (const float*)d_in[5];
    const float* gb1    = (const float*)d_in[6];
    const float* gW2    = (const float*)d_in[7];
    const float* gb2    = (const float*)d_in[8];

    const int B = in_sizes[0] / DD;
    float* out   = (float*)d_out;
    float* outx  = out;
    float* outv  = out + (size_t)B * DD;
    float* outlp = out + (size_t)2 * B * DD;

    cudaFuncSetAttribute(ires_fused_kernel,
                         cudaFuncAttributeMaxDynamicSharedMemorySize,
                         SMEM_FLOATS * sizeof(float));

    // output slot 0: x passthrough
    cudaMemcpyAsync(outx, gx, (size_t)B * DD * sizeof(float), cudaMemcpyDeviceToDevice);

    ires_fused_kernel<<<B / MT, 256, SMEM_FLOATS * sizeof(float)>>>(
        gx, gu, glogpx, geps, gW1x, gW1u, gb1, gW2, gb2, outv, outlp);
}

// round 16
// speedup vs baseline: 1.3418x; 1.3418x over previous
#include <cuda_runtime.h>
#include <math.h>
#include <stdint.h>

#define DD 64
#define HH 256
#define MT 32
#define NPS 10

// ---- shared memory layout (float offsets) ----
#define OFF_W2C   0        // series GEMM1 B: W2c[d][h] fp32 [64][264]; aliased in phase A: BUF [64][33]
#define W2C_STR   264
#define OFF_BUF   0
#define BUF_STR   33
#define OFF_R2    16896    // phase A: W1x/W1u natural [64][256] (stride 256), W2 natural [256][64] (stride 64);
                           // series: W1uT [256][72] (GEMM2 B)
#define W1UT_STR  72
#define OFF_T     35328    // [32][260]
#define T_STR     260
#define OFF_S     43648    // [32][260]
#define S_STR     260
#define OFF_WS    51968    // w tile natural [32][68]
#define WS_STR    68
#define OFF_EPS   54144    // eps natural [32][68]
#define EPS_STR   68
#define OFF_RED   56320    // [8][33] logdet partials
#define SMEM_FLOATS 56592  // 226368 bytes

__device__ __forceinline__ uint32_t f2tf32(float x) {
    uint32_t r; asm("cvt.rna.tf32.f32 %0, %1;" : "=r"(r) : "f"(x)); return r;
}
__device__ __forceinline__ void split_tf32(float x, uint32_t& hi, uint32_t& lo) {
    hi = f2tf32(x);
    lo = __float_as_uint(x - __uint_as_float(hi));  // HW truncates operand to tf32
}
__device__ __forceinline__ void mma8(float* c, uint32_t a0, uint32_t a1, uint32_t a2, uint32_t a3,
                                     uint32_t b0, uint32_t b1) {
    asm volatile("mma.sync.aligned.m16n8k8.row.col.f32.tf32.tf32.f32 "
                 "{%0,%1,%2,%3}, {%4,%5,%6,%7}, {%8,%9}, {%0,%1,%2,%3};\n"
                 : "+f"(c[0]), "+f"(c[1]), "+f"(c[2]), "+f"(c[3])
                 : "r"(a0), "r"(a1), "r"(a2), "r"(a3), "r"(b0), "r"(b1));
}

__global__ __launch_bounds__(256, 1)
void ires_fused_kernel(const float* __restrict__ gx, const float* __restrict__ gu,
                       const float* __restrict__ glogpx, const float* __restrict__ geps,
                       const float* __restrict__ gW1x, const float* __restrict__ gW1u,
                       const float* __restrict__ gb1, const float* __restrict__ gW2,
                       const float* __restrict__ gb2,
                       float* __restrict__ outv, float* __restrict__ outlp)
{
    extern __shared__ float sm[];
    const int tid = threadIdx.x;
    const int wn  = tid >> 5;   // warp 0..7
    const int ln  = tid & 31;   // lane
    const int g   = ln >> 2;    // mma group 0..7
    const int t   = ln & 3;     // mma thread-in-group 0..3
    const int m0  = blockIdx.x * MT;

    // ---------------- step 0: loads ----------------
    // W1x natural [64][256] -> R2
    #pragma unroll 4
    for (int i = 0; i < 64; i++) {
        int idx = tid + i * 256;
        sm[OFF_R2 + idx] = gW1x[idx];
    }
    // x transposed -> BUF
    #pragma unroll
    for (int i = 0; i < 8; i++) {
        int idx = tid + i * 256;
        int m = idx >> 6, d = idx & 63;
        sm[OFF_BUF + d * BUF_STR + m] = gx[(size_t)m0 * DD + idx];
    }
    // eps natural -> EPS and wS (w_0 = eps)
    #pragma unroll
    for (int i = 0; i < 8; i++) {
        int idx = tid + i * 256;
        float e = geps[(size_t)m0 * DD + idx];
        int m = idx >> 6, d = idx & 63;
        sm[OFF_EPS + m * EPS_STR + d] = e;
        sm[OFF_WS  + m * WS_STR  + d] = e;
    }
    __syncthreads();

    // ---------------- phase A: pre = x@W1x ----------------
    float pr[4][8];
    #pragma unroll
    for (int i = 0; i < 4; i++)
        #pragma unroll
        for (int j = 0; j < 8; j++) pr[i][j] = 0.f;

    #pragma unroll 8
    for (int d = 0; d < 64; d++) {
        float av[4];
        #pragma unroll
        for (int i = 0; i < 4; i++) av[i] = sm[OFF_BUF + d * BUF_STR + 4 * wn + i];
        float4 b04 = *(const float4*)&sm[OFF_R2 + d * HH + 8 * ln];
        float4 b14 = *(const float4*)&sm[OFF_R2 + d * HH + 8 * ln + 4];
        float bv[8] = {b04.x, b04.y, b04.z, b04.w, b14.x, b14.y, b14.z, b14.w};
        #pragma unroll
        for (int i = 0; i < 4; i++)
            #pragma unroll
            for (int j = 0; j < 8; j++)
                pr[i][j] = fmaf(av[i], bv[j], pr[i][j]);
    }
    __syncthreads();

    // load W1u natural -> R2, uT -> BUF
    #pragma unroll 4
    for (int i = 0; i < 64; i++) {
        int idx = tid + i * 256;
        sm[OFF_R2 + idx] = gW1u[idx];
    }
    #pragma unroll
    for (int i = 0; i < 8; i++) {
        int idx = tid + i * 256;
        int m = idx >> 6, d = idx & 63;
        sm[OFF_BUF + d * BUF_STR + m] = gu[(size_t)m0 * DD + idx];
    }
    __syncthreads();

    // pre += u@W1u
    #pragma unroll 8
    for (int d = 0; d < 64; d++) {
        float av[4];
        #pragma unroll
        for (int i = 0; i < 4; i++) av[i] = sm[OFF_BUF + d * BUF_STR + 4 * wn + i];
        float4 b04 = *(const float4*)&sm[OFF_R2 + d * HH + 8 * ln];
        float4 b14 = *(const float4*)&sm[OFF_R2 + d * HH + 8 * ln + 4];
        float bv[8] = {b04.x, b04.y, b04.z, b04.w, b14.x, b14.y, b14.z, b14.w};
        #pragma unroll
        for (int i = 0; i < 4; i++)
            #pragma unroll
            for (int j = 0; j < 8; j++)
                pr[i][j] = fmaf(av[i], bv[j], pr[i][j]);
    }

    // + b1, then h = elu(pre) -> T,  s = elu'(pre) -> S
    {
        float4 bb0 = *(const float4*)&gb1[8 * ln];
        float4 bb1 = *(const float4*)&gb1[8 * ln + 4];
        float bb[8] = {bb0.x, bb0.y, bb0.z, bb0.w, bb1.x, bb1.y, bb1.z, bb1.w};
        #pragma unroll
        for (int i = 0; i < 4; i++) {
            float hv[8], sv[8];
            #pragma unroll
            for (int j = 0; j < 8; j++) {
                float p = pr[i][j] + bb[j];
                if (p > 0.f) { hv[j] = p; sv[j] = 1.f; }
                else { float em = expm1f(p); hv[j] = em; sv[j] = em + 1.f; }
            }
            int baseT = (4 * wn + i) * T_STR + 8 * ln;
            int baseS = (4 * wn + i) * S_STR + 8 * ln;
            *(float4*)&sm[OFF_T + baseT]     = make_float4(hv[0], hv[1], hv[2], hv[3]);
            *(float4*)&sm[OFF_T + baseT + 4] = make_float4(hv[4], hv[5], hv[6], hv[7]);
            *(float4*)&sm[OFF_S + baseS]     = make_float4(sv[0], sv[1], sv[2], sv[3]);
            *(float4*)&sm[OFF_S + baseS + 4] = make_float4(sv[4], sv[5], sv[6], sv[7]);
        }
    }
    __syncthreads();

    // load W2 natural [256][64] -> R2 (stride 64)
    #pragma unroll 4
    for (int i = 0; i < 64; i++) {
        int idx = tid + i * 256;
        sm[OFF_R2 + idx] = gW2[idx];
    }
    __syncthreads();

    // ---------------- g = h@W2 + b2 ; v = u + g ----------------
    {
        float ga[4][2];
        #pragma unroll
        for (int i = 0; i < 4; i++) { ga[i][0] = 0.f; ga[i][1] = 0.f; }
        #pragma unroll 2
        for (int h = 0; h < HH; h += 4) {
            float4 a0 = *(const float4*)&sm[OFF_T + (4 * wn + 0) * T_STR + h];
            float4 a1 = *(const float4*)&sm[OFF_T + (4 * wn + 1) * T_STR + h];
            float4 a2 = *(const float4*)&sm[OFF_T + (4 * wn + 2) * T_STR + h];
            float4 a3 = *(const float4*)&sm[OFF_T + (4 * wn + 3) * T_STR + h];
#define GSTEP(hh, c0, c1, c2, c3) { \
            float2 b = *(const float2*)&sm[OFF_R2 + (h + hh) * DD + 2 * ln]; \
            ga[0][0] = fmaf(c0, b.x, ga[0][0]); ga[0][1] = fmaf(c0, b.y, ga[0][1]); \
            ga[1][0] = fmaf(c1, b.x, ga[1][0]); ga[1][1] = fmaf(c1, b.y, ga[1][1]); \
            ga[2][0] = fmaf(c2, b.x, ga[2][0]); ga[2][1] = fmaf(c2, b.y, ga[2][1]); \
            ga[3][0] = fmaf(c3, b.x, ga[3][0]); ga[3][1] = fmaf(c3, b.y, ga[3][1]); }
            GSTEP(0, a0.x, a1.x, a2.x, a3.x)
            GSTEP(1, a0.y, a1.y, a2.y, a3.y)
            GSTEP(2, a0.z, a1.z, a2.z, a3.z)
            GSTEP(3, a0.w, a1.w, a2.w, a3.w)
#undef GSTEP
        }
        float2 b2v = *(const float2*)&gb2[2 * ln];
        #pragma unroll
        for (int i = 0; i < 4; i++) {
            size_t off = (size_t)(m0 + 4 * wn + i) * DD + 2 * ln;
            float2 uu = *(const float2*)&gu[off];
            float2 vv = make_float2(uu.x + ga[i][0] + b2v.x, uu.y + ga[i][1] + b2v.y);
            *(float2*)&outv[off] = vv;
        }
    }

    // build W2C[d][h] = W2nat[h][d] from R2 (smem->smem transpose); W2C region (=BUF alias) is dead
    #pragma unroll 4
    for (int i = 0; i < 64; i++) {
        int idx = tid + i * 256;
        int h = idx >> 6, d = idx & 63;
        sm[OFF_W2C + d * W2C_STR + h] = sm[OFF_R2 + idx];
    }
    __syncthreads();   // all reads of R2 (W2 natural) complete

    // load W1uT[h][d] [256][72] into R2 region (gW1u is [64][256] row-major)
    #pragma unroll 4
    for (int i = 0; i < 64; i++) {
        int idx = tid + i * 256;
        int d = idx >> 8, h = idx & 255;
        sm[OFF_R2 + h * W1UT_STR + d] = gW1u[idx];
    }
    __syncthreads();

    // ---------------- power series: 10 VJP iterations (tensor cores, 3xTF32) ----------------
    float ld[2][2] = {{0.f, 0.f}, {0.f, 0.f}};   // rows {g, g+8, 16+g, 24+g}

    for (int k = 1; k <= NPS; k++) {
        // === GEMM1: C1[32,256] = wS[32,64] @ W2C[64,256], warp wn owns h-cols [32wn, 32wn+32) ===
        float acc1[2][4][4];
        #pragma unroll
        for (int mi = 0; mi < 2; mi++)
            #pragma unroll
            for (int nt = 0; nt < 4; nt++)
                #pragma unroll
                for (int q = 0; q < 4; q++) acc1[mi][nt][q] = 0.f;

        #pragma unroll
        for (int kk = 0; kk < 8; kk++) {
            uint32_t Ah[2][4], Al[2][4];
            #pragma unroll
            for (int mi = 0; mi < 2; mi++) {
                int r0 = OFF_WS + (mi * 16 + g) * WS_STR + kk * 8 + t;
                split_tf32(sm[r0],                  Ah[mi][0], Al[mi][0]);
                split_tf32(sm[r0 + 8 * WS_STR],     Ah[mi][1], Al[mi][1]);
                split_tf32(sm[r0 + 4],              Ah[mi][2], Al[mi][2]);
                split_tf32(sm[r0 + 8 * WS_STR + 4], Ah[mi][3], Al[mi][3]);
            }
            #pragma unroll
            for (int nt = 0; nt < 4; nt++) {
                int bix = OFF_W2C + (kk * 8 + t) * W2C_STR + wn * 32 + nt * 8 + g;
                uint32_t Bh0, Bl0, Bh1, Bl1;
                split_tf32(sm[bix],                 Bh0, Bl0);
                split_tf32(sm[bix + 4 * W2C_STR],   Bh1, Bl1);
                #pragma unroll
                for (int mi = 0; mi < 2; mi++) {
                    mma8(acc1[mi][nt], Ah[mi][0], Ah[mi][1], Ah[mi][2], Ah[mi][3], Bh0, Bh1);
                    mma8(acc1[mi][nt], Al[mi][0], Al[mi][1], Al[mi][2], Al[mi][3], Bh0, Bh1);
                    mma8(acc1[mi][nt], Ah[mi][0], Ah[mi][1], Ah[mi][2], Ah[mi][3], Bl0, Bl1);
                }
            }
        }

        // t[m][h] = s[m][h] * c1[m][h] -> T
        #pragma unroll
        for (int mi = 0; mi < 2; mi++) {
            #pragma unroll
            for (int nt = 0; nt < 4; nt++) {
                int row = mi * 16 + g;
                int col = wn * 32 + nt * 8 + 2 * t;
                float2 s01 = *(const float2*)&sm[OFF_S + row * S_STR + col];
                float2 s23 = *(const float2*)&sm[OFF_S + (row + 8) * S_STR + col];
                *(float2*)&sm[OFF_T + row * T_STR + col] =
                    make_float2(acc1[mi][nt][0] * s01.x, acc1[mi][nt][1] * s01.y);
                *(float2*)&sm[OFF_T + (row + 8) * T_STR + col] =
                    make_float2(acc1[mi][nt][2] * s23.x, acc1[mi][nt][3] * s23.y);
            }
        }
        __syncthreads();

        // === GEMM2: w'[32,64] = T[32,256] @ W1uT[256,64], warp wn owns cols [8wn, 8wn+8) ===
        float acc2[2][4];
        #pragma unroll
        for (int mi = 0; mi < 2; mi++)
            #pragma unroll
            for (int q = 0; q < 4; q++) acc2[mi][q] = 0.f;

        #pragma unroll 8
        for (int kk = 0; kk < 32; kk++) {
            int bix = OFF_R2 + (kk * 8 + t) * W1UT_STR + wn * 8 + g;
            uint32_t Bh0, Bl0, Bh1, Bl1;
            split_tf32(sm[bix],                 Bh0, Bl0);
            split_tf32(sm[bix + 4 * W1UT_STR],  Bh1, Bl1);
            #pragma unroll
            for (int mi = 0; mi < 2; mi++) {
                int r0 = OFF_T + (mi * 16 + g) * T_STR + kk * 8 + t;
                uint32_t Ah0, Al0, Ah1, Al1, Ah2, Al2, Ah3, Al3;
                split_tf32(sm[r0],                 Ah0, Al0);
                split_tf32(sm[r0 + 8 * T_STR],     Ah1, Al1);
                split_tf32(sm[r0 + 4],             Ah2, Al2);
                split_tf32(sm[r0 + 8 * T_STR + 4], Ah3, Al3);
                mma8(acc2[mi], Ah0, Ah1, Ah2, Ah3, Bh0, Bh1);
                mma8(acc2[mi], Al0, Al1, Al2, Al3, Bh0, Bh1);
                mma8(acc2[mi], Ah0, Ah1, Ah2, Ah3, Bl0, Bl1);
            }
        }

        // logdet partial + write w' back to wS
        float coeff = ((k & 1) ? 1.0f : -1.0f) / (float)k;
        #pragma unroll
        for (int mi = 0; mi < 2; mi++) {
            int row = mi * 16 + g;
            int col = wn * 8 + 2 * t;
            float2 e01 = *(const float2*)&sm[OFF_EPS + row * EPS_STR + col];
            float2 e23 = *(const float2*)&sm[OFF_EPS + (row + 8) * EPS_STR + col];
            ld[mi][0] = fmaf(coeff, acc2[mi][0] * e01.x + acc2[mi][1] * e01.y, ld[mi][0]);
            ld[mi][1] = fmaf(coeff, acc2[mi][2] * e23.x + acc2[mi][3] * e23.y, ld[mi][1]);
            *(float2*)&sm[OFF_WS + row * WS_STR + col] = make_float2(acc2[mi][0], acc2[mi][1]);
            *(float2*)&sm[OFF_WS + (row + 8) * WS_STR + col] = make_float2(acc2[mi][2], acc2[mi][3]);
        }
        __syncthreads();
    }

    // ---------------- logdet reduction + output ----------------
    #pragma unroll
    for (int mi = 0; mi < 2; mi++)
        #pragma unroll
        for (int ri = 0; ri < 2; ri++) {
            ld[mi][ri] += __shfl_xor_sync(0xffffffffu, ld[mi][ri], 1);
            ld[mi][ri] += __shfl_xor_sync(0xffffffffu, ld[mi][ri], 2);
        }
    if (t == 0) {
        sm[OFF_RED + wn * 33 + g]      = ld[0][0];
        sm[OFF_RED + wn * 33 + g + 8]  = ld[0][1];
        sm[OFF_RED + wn * 33 + g + 16] = ld[1][0];
        sm[OFF_RED + wn * 33 + g + 24] = ld[1][1];
    }
    __syncthreads();
    if (tid < 32) {
        float s = 0.f;
        #pragma unroll
        for (int w = 0; w < 8; w++) s += sm[OFF_RED + w * 33 + tid];
        outlp[m0 + tid] = glogpx[m0 + tid] - s;
    }
}

extern "C" void kernel_launch(void* const* d_in, const int* in_sizes, int n_in,
                              void* d_out, int out_size)
{
    const float* gx     = (const float*)d_in[0];
    const float* gu     = (const float*)d_in[1];
    const float* glogpx = (const float*)d_in[2];
    const float* geps   = (const float*)d_in[3];
    const float* gW1x   = (const float*)d_in[4];
    const float* gW1u   = (const float*)d_in[5];
    const float* gb1    = (const float*)d_in[6];
    const float* gW2    = (const float*)d_in[7];
    const float* gb2    = (const float*)d_in[8];

    const int B = in_sizes[0] / DD;
    float* out   = (float*)d_out;
    float* outx  = out;
    float* outv  = out + (size_t)B * DD;
    float* outlp = out + (size_t)2 * B * DD;

    cudaFuncSetAttribute(ires_fused_kernel,
                         cudaFuncAttributeMaxDynamicSharedMemorySize,
                         SMEM_FLOATS * sizeof(float));

    // output slot 0: x passthrough
    cudaMemcpyAsync(outx, gx, (size_t)B * DD * sizeof(float), cudaMemcpyDeviceToDevice);

    ires_fused_kernel<<<B / MT, 256, SMEM_FLOATS * sizeof(float)>>>(
        gx, gu, glogpx, geps, gW1x, gW1u, gb1, gW2, gb2, outv, outlp);
}